// round 6
// baseline (speedup 1.0000x reference)
#include <cuda_runtime.h>
#include <cuda_bf16.h>
#include <cstdint>

#define Bn 1024
#define Sn 128
#define Dn 768
#define Cn 56
#define KC 32
#define NCHUNK 24
#define NBUF 2
#define AST (Sn * KC)           /* floats per A stage = 4096 (16KB) */
#define BROW 40                 /* bf16 per B row (32 data + 8 pad) */
#define BST (Cn * BROW)         /* bf16 per B stage = 2240 */
#define A_BYTES (NBUF * AST * 4)      /* 32768 */
#define B_BYTES (NBUF * BST * 2)      /* 8960  */
#define SMEM_DYN (A_BYTES + B_BYTES)  /* 41728 */

// Packed bf16 weight matrix W[c][d_logical], c in [0,56).
// k-columns PERMUTED within each 16-block so a lane's float4 A-load at
// phys col 4*t4 (+16s) directly yields the mma fragment's logical k pairs.
__device__ __nv_bfloat16 g_Wb[Cn * Dn];

__global__ void build_w_kernel(const float* __restrict__ w2, const float* __restrict__ w3,
                               const float* __restrict__ w4, const float* __restrict__ w5) {
    int i = blockIdx.x * blockDim.x + threadIdx.x;
    if (i >= Cn * Dn) return;
    int c = i / Dn, d = i % Dn;          // d = logical k index
    int blk = d >> 4, l = d & 15;
    int p = (l < 8) ? (((l >> 1) << 2) + (l & 1))
                    : ((((l - 8) >> 1) << 2) + 2 + (l & 1));
    int dp = (blk << 4) + p;             // physical k column in original weights
    float v;
    if (c < 8)       { int f = c / 2;        int j = c % 2;        v = w2[(f * Dn + dp) * 2 + j]; }
    else if (c < 20) { int cc = c - 8;  int f = cc / 3; int j = cc % 3; v = w3[(f * Dn + dp) * 3 + j]; }
    else if (c < 36) { int cc = c - 20; int f = cc / 4; int j = cc % 4; v = w4[(f * Dn + dp) * 4 + j]; }
    else             { int cc = c - 36; int f = cc / 5; int j = cc % 5; v = w5[(f * Dn + dp) * 5 + j]; }
    g_Wb[c * Dn + d] = __float2bfloat16(v);
}

__device__ __forceinline__ uint32_t f2bf2(float lo, float hi) {
    __nv_bfloat162 h = __float22bfloat162_rn(make_float2(lo, hi));
    return *reinterpret_cast<uint32_t*>(&h);
}

__device__ __forceinline__ void cp16(uint32_t dst_smem, const void* src) {
    asm volatile("cp.async.cg.shared.global [%0], [%1], 16;\n" :: "r"(dst_smem), "l"(src));
}

__global__ __launch_bounds__(256, 4) void fused_kernel(
    const int* __restrict__ x, const float* __restrict__ hidden,
    const float* __restrict__ b2, const float* __restrict__ b3,
    const float* __restrict__ b4, const float* __restrict__ b5,
    const float* __restrict__ fcw, const float* __restrict__ fcb,
    float* __restrict__ out)
{
    extern __shared__ __align__(16) unsigned char sraw[];
    float* As = reinterpret_cast<float*>(sraw);                        // [NBUF][128][32], XOR-swizzled
    __nv_bfloat16* Bsm = reinterpret_cast<__nv_bfloat16*>(sraw + A_BYTES); // [NBUF][56][40]
    float (*Psm)[Cn + 1] = reinterpret_cast<float (*)[Cn + 1]>(sraw);  // epilogue reuse of A region

    __shared__ int order[Sn];
    __shared__ unsigned mask4[4];
    __shared__ int sh_len;
    __shared__ float feats[16];

    const int b    = blockIdx.x;
    const int tid  = threadIdx.x;
    const int warp = tid >> 5;
    const int lane = tid & 31;
    const int g    = lane >> 2;   // 0..7
    const int t4   = lane & 3;    // 0..3

    const uint32_t a_base = (uint32_t)__cvta_generic_to_shared(As);
    const uint32_t b_base = (uint32_t)__cvta_generic_to_shared(Bsm);
    const float* hidb = hidden + (long)b * Sn * Dn;

    // ---- hoisted per-thread staging offsets (constant across chunks) ----
    uint32_t a_dst[4];      // swizzled byte offset within an A stage
    long     a_src[4];      // float offset within hidden row-block
    #pragma unroll
    for (int p = 0; p < 4; p++) {
        int u = tid + p * 256;          // 0..1023
        int r = u >> 3, q = u & 7;      // row, 16B-granule within row
        int rg = r & 7;
        int pmr = ((rg & 1) << 2) | (rg >> 1);
        a_dst[p] = (uint32_t)(r * KC + 4 * (q ^ pmr)) * 4;
        a_src[p] = (long)r * Dn + q * 4;
    }
    const int bc = tid >> 2, bq = tid & 3;                 // B: 224 threads used
    const uint32_t b_dst = (uint32_t)(bc * BROW + bq * 8) * 2;
    const __nv_bfloat16* b_src = g_Wb + bc * Dn + bq * 8;

    auto issueAB = [&](int ci, int buf) {
        const float* hsrc = hidb + ci * KC;
        #pragma unroll
        for (int p = 0; p < 4; p++)
            cp16(a_base + (uint32_t)(buf * AST * 4) + a_dst[p], hsrc + a_src[p]);
        if (tid < 224)
            cp16(b_base + (uint32_t)(buf * BST * 2) + b_dst, b_src + ci * KC);
        asm volatile("cp.async.commit_group;\n");
    };

    issueAB(0, 0);

    // ---- stable compaction order (overlaps with first load) ----
    if (tid < Sn) {
        int nz = (x[b * Sn + tid] != 0);
        unsigned m = __ballot_sync(0xFFFFFFFFu, nz);
        if (lane == 0) mask4[warp] = m;
    }
    __syncthreads();
    if (tid < Sn) {
        unsigned mw = mask4[warp];
        int nzbefore = __popc(mw & ((1u << lane) - 1u));
        int nztot_before = 0, total = 0;
        #pragma unroll
        for (int w = 0; w < 4; w++) { if (w < warp) nztot_before += __popc(mask4[w]); total += __popc(mask4[w]); }
        int isnz = (mw >> lane) & 1;
        int pos = isnz ? (nztot_before + nzbefore)
                       : (total + (tid - nztot_before - nzbefore));
        order[pos] = tid;
        if (tid == 0) sh_len = total;
    }

    // ---- GEMM mainloop (double buffer, prefetch distance 1) ----
    float acc[7][4];
    #pragma unroll
    for (int j = 0; j < 7; j++)
        #pragma unroll
        for (int q = 0; q < 4; q++) acc[j][q] = 0.0f;

    const int pm = ((g & 1) << 2) | (g >> 1);
    const int rowA = warp * 16 + g;

    #pragma unroll 1
    for (int ci = 0; ci < NCHUNK; ci++) {
        asm volatile("cp.async.wait_group 0;\n" ::: "memory");
        __syncthreads();   // single barrier per chunk

        if (ci + 1 < NCHUNK) issueAB(ci + 1, (ci + 1) & 1);

        const float* Abuf = As + (ci & 1) * AST;
        const __nv_bfloat16* Bbuf = Bsm + (ci & 1) * BST;

        #pragma unroll
        for (int s = 0; s < 2; s++) {
            int q0 = (t4 + 4 * s) ^ pm;
            float4 f0 = *(const float4*)(Abuf + rowA * KC + 4 * q0);
            float4 f1 = *(const float4*)(Abuf + (rowA + 8) * KC + 4 * q0);
            uint32_t a0 = f2bf2(f0.x, f0.y), a2 = f2bf2(f0.z, f0.w);
            uint32_t a1 = f2bf2(f1.x, f1.y), a3 = f2bf2(f1.z, f1.w);
            #pragma unroll
            for (int j = 0; j < 7; j++) {
                const __nv_bfloat16* brow = Bbuf + (8 * j + g) * BROW + 16 * s + 2 * t4;
                uint32_t bb0 = *(const uint32_t*)brow;
                uint32_t bb1 = *(const uint32_t*)(brow + 8);
                asm volatile(
                    "mma.sync.aligned.m16n8k16.row.col.f32.bf16.bf16.f32 "
                    "{%0,%1,%2,%3}, {%4,%5,%6,%7}, {%8,%9}, {%0,%1,%2,%3};\n"
                    : "+f"(acc[j][0]), "+f"(acc[j][1]), "+f"(acc[j][2]), "+f"(acc[j][3])
                    : "r"(a0), "r"(a1), "r"(a2), "r"(a3), "r"(bb0), "r"(bb1));
            }
        }
    }

    // ---- all warps done with As before Psm overwrites it ----
    __syncthreads();
    #pragma unroll
    for (int j = 0; j < 7; j++) {
        int c = j * 8 + 2 * t4;
        Psm[rowA][c]         = acc[j][0];
        Psm[rowA][c + 1]     = acc[j][1];
        Psm[rowA + 8][c]     = acc[j][2];
        Psm[rowA + 8][c + 1] = acc[j][3];
    }
    __syncthreads();

    // ---- ragged conv + max-pool: 16 features, 2 per warp ----
    const int L = sh_len;
    #pragma unroll
    for (int r = 0; r < 2; r++) {
        int fi = warp + r * 8;
        int kk = fi / 4 + 2;
        int f  = fi % 4;
        int cb = (kk == 2 ? 0 : (kk == 3 ? 8 : (kk == 4 ? 20 : 36))) + f * kk;
        const float* bptr = (kk == 2 ? b2 : (kk == 3 ? b3 : (kk == 4 ? b4 : b5)));
        float bias = bptr[f];
        int nt = L - kk + 1;
        float m = -1e30f;
        for (int tp = lane; tp < nt; tp += 32) {
            float sconv = bias;
            for (int j = 0; j < kk; j++)
                sconv += Psm[order[tp + j]][cb + j];
            m = fmaxf(m, sconv);
        }
        #pragma unroll
        for (int off = 16; off; off >>= 1)
            m = fmaxf(m, __shfl_xor_sync(0xFFFFFFFFu, m, off));
        if (lane == 0) feats[fi] = m;
    }
    __syncthreads();

    if (tid == 0) {
        float z = fcb[0];
        #pragma unroll
        for (int i = 0; i < 16; i++) z += feats[i] * fcw[i];
        out[b] = 1.0f / (1.0f + expf(-z));
    }
}

extern "C" void kernel_launch(void* const* d_in, const int* in_sizes, int n_in,
                              void* d_out, int out_size) {
    const int*   x      = (const int*)d_in[0];
    const float* hidden = (const float*)d_in[1];
    const float* w2     = (const float*)d_in[2];
    const float* b2     = (const float*)d_in[3];
    const float* w3     = (const float*)d_in[4];
    const float* b3     = (const float*)d_in[5];
    const float* w4     = (const float*)d_in[6];
    const float* b4     = (const float*)d_in[7];
    const float* w5     = (const float*)d_in[8];
    const float* b5     = (const float*)d_in[9];
    const float* fcw    = (const float*)d_in[10];
    const float* fcb    = (const float*)d_in[11];
    float* out = (float*)d_out;

    cudaFuncSetAttribute(fused_kernel, cudaFuncAttributeMaxDynamicSharedMemorySize, SMEM_DYN);

    build_w_kernel<<<(Cn * Dn + 255) / 256, 256>>>(w2, w3, w4, w5);
    fused_kernel<<<Bn, 256, SMEM_DYN>>>(x, hidden, b2, b3, b4, b5, fcw, fcb, out);
}

// round 7
// speedup vs baseline: 1.1021x; 1.1021x over previous
#include <cuda_runtime.h>
#include <cuda_bf16.h>
#include <cstdint>

#define Bn 1024
#define Sn 128
#define Dn 768
#define Cn 56
#define KC 16
#define NCHUNK 48
#define NBUF 4
#define AST (Sn * KC)                 /* floats per A stage = 2048 (8KB) */
#define BROW 24                       /* bf16 per B row (16 data + 8 pad), 48B stride */
#define BST (Cn * BROW)               /* bf16 per B stage = 1344 (2688B) */
#define A_BYTES (NBUF * AST * 4)      /* 32768 */
#define B_BYTES (NBUF * BST * 2)      /* 10752 */
#define SMEM_DYN (A_BYTES + B_BYTES)  /* 43520 -> 4 CTAs/SM */

// Packed bf16 weight matrix W[c][d_logical], c in [0,56).
// k-columns PERMUTED within each 16-block: lane t4's float4 at phys col 4*t4
// yields the mma fragment's logical k pairs {2t4,2t4+1} / {2t4+8,2t4+9}.
__device__ __nv_bfloat16 g_Wb[Cn * Dn];

__global__ void build_w_kernel(const float* __restrict__ w2, const float* __restrict__ w3,
                               const float* __restrict__ w4, const float* __restrict__ w5) {
    int i = blockIdx.x * blockDim.x + threadIdx.x;
    if (i >= Cn * Dn) return;
    int c = i / Dn, d = i % Dn;          // d = logical k index
    int blk = d >> 4, l = d & 15;
    int p = (l < 8) ? (((l >> 1) << 2) + (l & 1))
                    : ((((l - 8) >> 1) << 2) + 2 + (l & 1));
    int dp = (blk << 4) + p;             // physical k column in original weights
    float v;
    if (c < 8)       { int f = c / 2;        int j = c % 2;        v = w2[(f * Dn + dp) * 2 + j]; }
    else if (c < 20) { int cc = c - 8;  int f = cc / 3; int j = cc % 3; v = w3[(f * Dn + dp) * 3 + j]; }
    else if (c < 36) { int cc = c - 20; int f = cc / 4; int j = cc % 4; v = w4[(f * Dn + dp) * 4 + j]; }
    else             { int cc = c - 36; int f = cc / 5; int j = cc % 5; v = w5[(f * Dn + dp) * 5 + j]; }
    g_Wb[c * Dn + d] = __float2bfloat16(v);
}

__device__ __forceinline__ uint32_t f2bf2(float lo, float hi) {
    __nv_bfloat162 h = __float22bfloat162_rn(make_float2(lo, hi));
    return *reinterpret_cast<uint32_t*>(&h);
}

__device__ __forceinline__ void cp16(uint32_t dst_smem, const void* src) {
    asm volatile("cp.async.cg.shared.global [%0], [%1], 16;\n" :: "r"(dst_smem), "l"(src));
}

__global__ __launch_bounds__(256, 4) void fused_kernel(
    const int* __restrict__ x, const float* __restrict__ hidden,
    const float* __restrict__ b2, const float* __restrict__ b3,
    const float* __restrict__ b4, const float* __restrict__ b5,
    const float* __restrict__ fcw, const float* __restrict__ fcb,
    float* __restrict__ out)
{
    extern __shared__ __align__(16) unsigned char sraw[];
    float* As = reinterpret_cast<float*>(sraw);                            // [NBUF][128][16], no swizzle
    __nv_bfloat16* Bsm = reinterpret_cast<__nv_bfloat16*>(sraw + A_BYTES); // [NBUF][56][24]
    float (*Psm)[Cn + 1] = reinterpret_cast<float (*)[Cn + 1]>(sraw);      // epilogue reuse of A region

    __shared__ int order[Sn];
    __shared__ unsigned mask4[4];
    __shared__ int sh_len;
    __shared__ float feats[16];

    const int b    = blockIdx.x;
    const int tid  = threadIdx.x;
    const int warp = tid >> 5;
    const int lane = tid & 31;
    const int g    = lane >> 2;   // 0..7
    const int t4   = lane & 3;    // 0..3

    const uint32_t a_base = (uint32_t)__cvta_generic_to_shared(As);
    const uint32_t b_base = (uint32_t)__cvta_generic_to_shared(Bsm);
    const float* hidb = hidden + (long)b * Sn * Dn;

    // ---- hoisted per-thread staging offsets ----
    // A: 512 16B pieces (128 rows x 4 granules), 2 per thread
    const int  ar0 = tid >> 2, aq0 = tid & 3;             // rows 0..63
    const uint32_t a_d0 = (uint32_t)(ar0 * KC + 4 * aq0) * 4;
    const uint32_t a_d1 = a_d0 + (uint32_t)(64 * KC) * 4;
    const long a_s0 = (long)ar0 * Dn + 4 * aq0;
    const long a_s1 = a_s0 + 64L * Dn;
    // B: 112 16B pieces (56 rows x 2 granules)
    const int  brw = tid >> 1, bq = tid & 1;
    const uint32_t b_d = (uint32_t)(brw * BROW + 8 * bq) * 2;
    const __nv_bfloat16* b_s = g_Wb + brw * Dn + 8 * bq;

    auto issueAB = [&](int ci, int buf) {
        const float* hsrc = hidb + ci * KC;
        cp16(a_base + (uint32_t)(buf * AST * 4) + a_d0, hsrc + a_s0);
        cp16(a_base + (uint32_t)(buf * AST * 4) + a_d1, hsrc + a_s1);
        if (tid < 112)
            cp16(b_base + (uint32_t)(buf * BST * 2) + b_d, b_s + ci * KC);
        asm volatile("cp.async.commit_group;\n");
    };

    issueAB(0, 0);
    issueAB(1, 1);
    issueAB(2, 2);

    // ---- stable compaction order (overlaps with first loads) ----
    if (tid < Sn) {
        int nz = (x[b * Sn + tid] != 0);
        unsigned m = __ballot_sync(0xFFFFFFFFu, nz);
        if (lane == 0) mask4[warp] = m;
    }
    __syncthreads();
    if (tid < Sn) {
        unsigned mw = mask4[warp];
        int nzbefore = __popc(mw & ((1u << lane) - 1u));
        int nztot_before = 0, total = 0;
        #pragma unroll
        for (int w = 0; w < 4; w++) { if (w < warp) nztot_before += __popc(mask4[w]); total += __popc(mask4[w]); }
        int isnz = (mw >> lane) & 1;
        int pos = isnz ? (nztot_before + nzbefore)
                       : (total + (tid - nztot_before - nzbefore));
        order[pos] = tid;
        if (tid == 0) sh_len = total;
    }

    // ---- GEMM mainloop: 48 chunks, 4 buffers, prefetch distance 3 ----
    float acc[7][4];
    #pragma unroll
    for (int j = 0; j < 7; j++)
        #pragma unroll
        for (int q = 0; q < 4; q++) acc[j][q] = 0.0f;

    const int rowA = warp * 16 + g;

    #pragma unroll 1
    for (int ci = 0; ci < NCHUNK; ci++) {
        if (ci < NCHUNK - 2)      asm volatile("cp.async.wait_group 2;\n" ::: "memory");
        else if (ci == NCHUNK - 2) asm volatile("cp.async.wait_group 1;\n" ::: "memory");
        else                      asm volatile("cp.async.wait_group 0;\n" ::: "memory");
        __syncthreads();   // single barrier per chunk

        if (ci + 3 < NCHUNK) issueAB(ci + 3, (ci + 3) & (NBUF - 1));

        const float* Abuf = As + (ci & (NBUF - 1)) * AST;
        const __nv_bfloat16* Bbuf = Bsm + (ci & (NBUF - 1)) * BST;

        float4 f0 = *(const float4*)(Abuf + rowA * KC + 4 * t4);
        float4 f1 = *(const float4*)(Abuf + (rowA + 8) * KC + 4 * t4);
        uint32_t a0 = f2bf2(f0.x, f0.y), a2 = f2bf2(f0.z, f0.w);
        uint32_t a1 = f2bf2(f1.x, f1.y), a3 = f2bf2(f1.z, f1.w);
        #pragma unroll
        for (int j = 0; j < 7; j++) {
            const __nv_bfloat16* brow = Bbuf + (8 * j + g) * BROW + 2 * t4;
            uint32_t bb0 = *(const uint32_t*)brow;
            uint32_t bb1 = *(const uint32_t*)(brow + 8);
            asm volatile(
                "mma.sync.aligned.m16n8k16.row.col.f32.bf16.bf16.f32 "
                "{%0,%1,%2,%3}, {%4,%5,%6,%7}, {%8,%9}, {%0,%1,%2,%3};\n"
                : "+f"(acc[j][0]), "+f"(acc[j][1]), "+f"(acc[j][2]), "+f"(acc[j][3])
                : "r"(a0), "r"(a1), "r"(a2), "r"(a3), "r"(bb0), "r"(bb1));
        }
    }

    // ---- all warps done with As before Psm overwrites it ----
    __syncthreads();
    #pragma unroll
    for (int j = 0; j < 7; j++) {
        int c = j * 8 + 2 * t4;
        Psm[rowA][c]         = acc[j][0];
        Psm[rowA][c + 1]     = acc[j][1];
        Psm[rowA + 8][c]     = acc[j][2];
        Psm[rowA + 8][c + 1] = acc[j][3];
    }
    __syncthreads();

    // ---- ragged conv + max-pool: 16 features, 2 per warp ----
    const int L = sh_len;
    #pragma unroll
    for (int r = 0; r < 2; r++) {
        int fi = warp + r * 8;
        int kk = fi / 4 + 2;
        int f  = fi % 4;
        int cb = (kk == 2 ? 0 : (kk == 3 ? 8 : (kk == 4 ? 20 : 36))) + f * kk;
        const float* bptr = (kk == 2 ? b2 : (kk == 3 ? b3 : (kk == 4 ? b4 : b5)));
        float bias = bptr[f];
        int nt = L - kk + 1;
        float m = -1e30f;
        for (int tp = lane; tp < nt; tp += 32) {
            float sconv = bias;
            for (int j = 0; j < kk; j++)
                sconv += Psm[order[tp + j]][cb + j];
            m = fmaxf(m, sconv);
        }
        #pragma unroll
        for (int off = 16; off; off >>= 1)
            m = fmaxf(m, __shfl_xor_sync(0xFFFFFFFFu, m, off));
        if (lane == 0) feats[fi] = m;
    }
    __syncthreads();

    if (tid == 0) {
        float z = fcb[0];
        #pragma unroll
        for (int i = 0; i < 16; i++) z += feats[i] * fcw[i];
        out[b] = 1.0f / (1.0f + expf(-z));
    }
}

extern "C" void kernel_launch(void* const* d_in, const int* in_sizes, int n_in,
                              void* d_out, int out_size) {
    const int*   x      = (const int*)d_in[0];
    const float* hidden = (const float*)d_in[1];
    const float* w2     = (const float*)d_in[2];
    const float* b2     = (const float*)d_in[3];
    const float* w3     = (const float*)d_in[4];
    const float* b3     = (const float*)d_in[5];
    const float* w4     = (const float*)d_in[6];
    const float* b4     = (const float*)d_in[7];
    const float* w5     = (const float*)d_in[8];
    const float* b5     = (const float*)d_in[9];
    const float* fcw    = (const float*)d_in[10];
    const float* fcb    = (const float*)d_in[11];
    float* out = (float*)d_out;

    cudaFuncSetAttribute(fused_kernel, cudaFuncAttributeMaxDynamicSharedMemorySize, SMEM_DYN);

    build_w_kernel<<<(Cn * Dn + 255) / 256, 256>>>(w2, w3, w4, w5);
    fused_kernel<<<Bn, 256, SMEM_DYN>>>(x, hidden, b2, b3, b4, b5, fcw, fcb, out);
}

// round 8
// speedup vs baseline: 1.1864x; 1.0764x over previous
#include <cuda_runtime.h>
#include <cuda_bf16.h>
#include <cstdint>

#define Bn 1024
#define Sn 128
#define Dn 768
#define Cn 56
#define KC 16
#define NCHUNK 48
#define NBUF 5
#define AST (Sn * KC)                 /* floats per A stage = 2048 (8KB) */
#define BROW 16                       /* bf16 per B row, 32B stride, no pad */
#define BST (Cn * BROW)               /* bf16 per B stage = 896 (1792B) */
#define A_BYTES (NBUF * AST * 4)      /* 40960 */
#define B_BYTES (NBUF * BST * 2)      /* 8960  */
#define SMEM_DYN (A_BYTES + B_BYTES)  /* 49920 -> 4 CTAs/SM */

// Raw bf16 weight matrix W[c][k], c in [0,56), k physical order (no permute:
// A-fragment slots map to phys cols {4t4,4t4+1}=a0/bb0-lo, {4t4+2,4t4+3}=a2/bb1,
// so B fragments are contiguous 8B -> one LDS.64 per j).
__device__ __nv_bfloat16 g_Wb[Cn * Dn];

__global__ void build_w_kernel(const float* __restrict__ w2, const float* __restrict__ w3,
                               const float* __restrict__ w4, const float* __restrict__ w5) {
    int i = blockIdx.x * blockDim.x + threadIdx.x;
    if (i >= Cn * Dn) return;
    int c = i / Dn, d = i % Dn;
    float v;
    if (c < 8)       { int f = c / 2;        int j = c % 2;        v = w2[(f * Dn + d) * 2 + j]; }
    else if (c < 20) { int cc = c - 8;  int f = cc / 3; int j = cc % 3; v = w3[(f * Dn + d) * 3 + j]; }
    else if (c < 36) { int cc = c - 20; int f = cc / 4; int j = cc % 4; v = w4[(f * Dn + d) * 4 + j]; }
    else             { int cc = c - 36; int f = cc / 5; int j = cc % 5; v = w5[(f * Dn + d) * 5 + j]; }
    g_Wb[c * Dn + d] = __float2bfloat16(v);
}

__device__ __forceinline__ uint32_t f2bf2(float lo, float hi) {
    __nv_bfloat162 h = __float22bfloat162_rn(make_float2(lo, hi));
    return *reinterpret_cast<uint32_t*>(&h);
}

__device__ __forceinline__ void cp16(uint32_t dst_smem, const void* src) {
    asm volatile("cp.async.cg.shared.global [%0], [%1], 16;\n" :: "r"(dst_smem), "l"(src));
}

__global__ __launch_bounds__(256, 4) void fused_kernel(
    const int* __restrict__ x, const float* __restrict__ hidden,
    const float* __restrict__ b2, const float* __restrict__ b3,
    const float* __restrict__ b4, const float* __restrict__ b5,
    const float* __restrict__ fcw, const float* __restrict__ fcb,
    float* __restrict__ out)
{
    extern __shared__ __align__(16) unsigned char sraw[];
    float* As = reinterpret_cast<float*>(sraw);                            // [NBUF][128][16]
    __nv_bfloat16* Bsm = reinterpret_cast<__nv_bfloat16*>(sraw + A_BYTES); // [NBUF][56][16]
    float (*Psm)[Cn + 1] = reinterpret_cast<float (*)[Cn + 1]>(sraw);      // epilogue reuse

    __shared__ int order[Sn];
    __shared__ unsigned mask4[4];
    __shared__ int sh_len;
    __shared__ float feats[16];

    const int b    = blockIdx.x;
    const int tid  = threadIdx.x;
    const int warp = tid >> 5;
    const int lane = tid & 31;
    const int g    = lane >> 2;   // 0..7
    const int t4   = lane & 3;    // 0..3

    const uint32_t a_base = (uint32_t)__cvta_generic_to_shared(As);
    const uint32_t b_base = (uint32_t)__cvta_generic_to_shared(Bsm);
    const float* hidb = hidden + (long)b * Sn * Dn;

    // hoisted per-thread staging offsets
    const int  ar0 = tid >> 2, aq0 = tid & 3;
    const uint32_t a_d0 = (uint32_t)(ar0 * KC + 4 * aq0) * 4;
    const uint32_t a_d1 = a_d0 + (uint32_t)(64 * KC) * 4;
    const long a_s0 = (long)ar0 * Dn + 4 * aq0;
    const long a_s1 = a_s0 + 64L * Dn;
    const int  brw = tid >> 1, bq = tid & 1;
    const uint32_t b_d = (uint32_t)(brw * BROW + 8 * bq) * 2;
    const __nv_bfloat16* b_s = g_Wb + brw * Dn + 8 * bq;

    auto issueAB = [&](int ci, int buf) {
        const float* hsrc = hidb + ci * KC;
        cp16(a_base + (uint32_t)(buf * AST * 4) + a_d0, hsrc + a_s0);
        cp16(a_base + (uint32_t)(buf * AST * 4) + a_d1, hsrc + a_s1);
        if (tid < 112)
            cp16(b_base + (uint32_t)(buf * BST * 2) + b_d, b_s + ci * KC);
        asm volatile("cp.async.commit_group;\n");
    };

    issueAB(0, 0);
    issueAB(1, 1);
    issueAB(2, 2);
    issueAB(3, 3);

    // ---- stable compaction order (overlaps with first loads) ----
    if (tid < Sn) {
        int nz = (x[b * Sn + tid] != 0);
        unsigned m = __ballot_sync(0xFFFFFFFFu, nz);
        if (lane == 0) mask4[warp] = m;
    }
    __syncthreads();
    if (tid < Sn) {
        unsigned mw = mask4[warp];
        int nzbefore = __popc(mw & ((1u << lane) - 1u));
        int nztot_before = 0, total = 0;
        #pragma unroll
        for (int w = 0; w < 4; w++) { if (w < warp) nztot_before += __popc(mask4[w]); total += __popc(mask4[w]); }
        int isnz = (mw >> lane) & 1;
        int pos = isnz ? (nztot_before + nzbefore)
                       : (total + (tid - nztot_before - nzbefore));
        order[pos] = tid;
        if (tid == 0) sh_len = total;
    }

    // ---- GEMM mainloop: 48 chunks, 5 buffers, prefetch distance 4 ----
    float acc[7][4];
    #pragma unroll
    for (int j = 0; j < 7; j++)
        #pragma unroll
        for (int q = 0; q < 4; q++) acc[j][q] = 0.0f;

    const int rowA = warp * 16 + g;
    const uint32_t a_off0 = (uint32_t)(rowA * KC + 4 * t4);
    const uint32_t a_off1 = a_off0 + 8 * KC;

    auto computeChunk = [&](int buf) {
        const float* Abuf = As + buf * AST;
        const __nv_bfloat16* Bbuf = Bsm + buf * BST;
        float4 f0 = *(const float4*)(Abuf + a_off0);
        float4 f1 = *(const float4*)(Abuf + a_off1);
        uint32_t a0 = f2bf2(f0.x, f0.y), a2 = f2bf2(f0.z, f0.w);
        uint32_t a1 = f2bf2(f1.x, f1.y), a3 = f2bf2(f1.z, f1.w);
        #pragma unroll
        for (int j = 0; j < 7; j++) {
            uint2 bb = *(const uint2*)(Bbuf + (8 * j + g) * BROW + 4 * t4);
            asm volatile(
                "mma.sync.aligned.m16n8k16.row.col.f32.bf16.bf16.f32 "
                "{%0,%1,%2,%3}, {%4,%5,%6,%7}, {%8,%9}, {%0,%1,%2,%3};\n"
                : "+f"(acc[j][0]), "+f"(acc[j][1]), "+f"(acc[j][2]), "+f"(acc[j][3])
                : "r"(a0), "r"(a1), "r"(a2), "r"(a3), "r"(bb.x), "r"(bb.y));
        }
    };

    int buf = 0;        // buffer of chunk ci
    int bufN = 4;       // buffer of chunk ci+4
    #pragma unroll 1
    for (int ci = 0; ci < NCHUNK - 4; ci++) {
        asm volatile("cp.async.wait_group 3;\n" ::: "memory");
        __syncthreads();
        issueAB(ci + 4, bufN);
        computeChunk(buf);
        if (++buf == NBUF) buf = 0;
        if (++bufN == NBUF) bufN = 0;
    }
    // tail: chunks 44..47 in buffers 4,0,1,2 (44 % 5 == 4)
    asm volatile("cp.async.wait_group 3;\n" ::: "memory");
    __syncthreads();
    computeChunk(4);
    asm volatile("cp.async.wait_group 2;\n" ::: "memory");
    __syncthreads();
    computeChunk(0);
    asm volatile("cp.async.wait_group 1;\n" ::: "memory");
    __syncthreads();
    computeChunk(1);
    asm volatile("cp.async.wait_group 0;\n" ::: "memory");
    __syncthreads();
    computeChunk(2);

    // ---- all warps done with As before Psm overwrites it ----
    __syncthreads();
    #pragma unroll
    for (int j = 0; j < 7; j++) {
        int c = j * 8 + 2 * t4;
        Psm[rowA][c]         = acc[j][0];
        Psm[rowA][c + 1]     = acc[j][1];
        Psm[rowA + 8][c]     = acc[j][2];
        Psm[rowA + 8][c + 1] = acc[j][3];
    }
    __syncthreads();

    // ---- ragged conv + max-pool: 16 features, 2 per warp ----
    const int L = sh_len;
    #pragma unroll
    for (int r = 0; r < 2; r++) {
        int fi = warp + r * 8;
        int kk = fi / 4 + 2;
        int f  = fi % 4;
        int cb = (kk == 2 ? 0 : (kk == 3 ? 8 : (kk == 4 ? 20 : 36))) + f * kk;
        const float* bptr = (kk == 2 ? b2 : (kk == 3 ? b3 : (kk == 4 ? b4 : b5)));
        float bias = bptr[f];
        int nt = L - kk + 1;
        float m = -1e30f;
        for (int tp = lane; tp < nt; tp += 32) {
            float sconv = bias;
            for (int j = 0; j < kk; j++)
                sconv += Psm[order[tp + j]][cb + j];
            m = fmaxf(m, sconv);
        }
        #pragma unroll
        for (int off = 16; off; off >>= 1)
            m = fmaxf(m, __shfl_xor_sync(0xFFFFFFFFu, m, off));
        if (lane == 0) feats[fi] = m;
    }
    __syncthreads();

    if (tid == 0) {
        float z = fcb[0];
        #pragma unroll
        for (int i = 0; i < 16; i++) z += feats[i] * fcw[i];
        out[b] = 1.0f / (1.0f + expf(-z));
    }
}

extern "C" void kernel_launch(void* const* d_in, const int* in_sizes, int n_in,
                              void* d_out, int out_size) {
    const int*   x      = (const int*)d_in[0];
    const float* hidden = (const float*)d_in[1];
    const float* w2     = (const float*)d_in[2];
    const float* b2     = (const float*)d_in[3];
    const float* w3     = (const float*)d_in[4];
    const float* b3     = (const float*)d_in[5];
    const float* w4     = (const float*)d_in[6];
    const float* b4     = (const float*)d_in[7];
    const float* w5     = (const float*)d_in[8];
    const float* b5     = (const float*)d_in[9];
    const float* fcw    = (const float*)d_in[10];
    const float* fcb    = (const float*)d_in[11];
    float* out = (float*)d_out;

    cudaFuncSetAttribute(fused_kernel, cudaFuncAttributeMaxDynamicSharedMemorySize, SMEM_DYN);

    build_w_kernel<<<(Cn * Dn + 255) / 256, 256>>>(w2, w3, w4, w5);
    fused_kernel<<<Bn, 256, SMEM_DYN>>>(x, hidden, b2, b3, b4, b5, fcw, fcb, out);
}